// round 5
// baseline (speedup 1.0000x reference)
#include <cuda_runtime.h>
#include <math.h>

#define NQ 8
#define NBLOCKS 1024
#define TPB 256

// ---- 8-point Gauss-Legendre (positive half; symmetric) ----
__device__ constexpr float GLX4[4] = {
    0.18343464249564980f, 0.52553240991632899f, 0.79666647741362674f, 0.96028985649753623f};
__device__ constexpr float GLW4[4] = {
    0.36268378337836198f, 0.31370664587788729f, 0.22238103445337447f, 0.10122853629037626f};

__device__ constexpr float hx_of(int q) {
    return (q < 4) ? 0.5f * (1.0f - GLX4[3 - q]) : 0.5f * (1.0f + GLX4[q - 4]);
}
__device__ constexpr float gw_of(int q) {
    return (q < 4) ? GLW4[3 - q] : GLW4[q - 4];
}

__device__ double d_part[NBLOCKS];
__device__ unsigned int d_count;   // zero-init; reset by last block each launch

__device__ __forceinline__ float ex2f(float x) {
    float y;
    asm("ex2.approx.ftz.f32 %0, %1;" : "=f"(y) : "f"(x));
    return y;
}
__device__ __forceinline__ float rcpf(float x) {
    float y;
    asm("rcp.approx.ftz.f32 %0, %1;" : "=f"(y) : "f"(x));
    return y;
}

// Acklam inverse-normal-CDF central region, takes q = p - 0.5 (|q| <= 0.45).
__device__ __forceinline__ float ninv_q(float q) {
    const float r = q * q;
    float num = fmaf(-3.969683028665376e+01f, r, 2.209460984245205e+02f);
    num = fmaf(num, r, -2.759285104469687e+02f);
    num = fmaf(num, r, 1.383577518672690e+02f);
    num = fmaf(num, r, -3.066479806614716e+01f);
    num = fmaf(num, r, 2.506628277459239e+00f);
    float den = fmaf(-5.447609879822406e+01f, r, 1.615858368580409e+02f);
    den = fmaf(den, r, -1.556989798598866e+02f);
    den = fmaf(den, r, 6.680131188771972e+01f);
    den = fmaf(den, r, -1.328068155288572e+01f);
    den = fmaf(den, r, 1.0f);
    return q * num * rcpf(den);
}

// Phi(h) via A&S 7.1.26 erfc (abs err <= 1.5e-7); eneg = exp(-h^2/2).
__device__ __forceinline__ float phi_fast(float h, float eneg) {
    const float z = fabsf(h) * 0.70710678118654752f;
    const float t = rcpf(fmaf(0.3275911f, z, 1.0f));
    float poly = fmaf(1.061405429f, t, -1.453152027f);
    poly = fmaf(poly, t, 1.421413741f);
    poly = fmaf(poly, t, -0.284496736f);
    poly = fmaf(poly, t, 0.254829592f);
    const float half_erfc = 0.5f * poly * t * eneg;
    return (h >= 0.0f) ? (1.0f - half_erfc) : half_erfc;
}

#define F4A(a, v) { a[0] = (v).x; a[1] = (v).y; a[2] = (v).z; a[3] = (v).w; }

__global__ __launch_bounds__(TPB, 3) void loss_kernel(
    const float* __restrict__ yhat, const float* __restrict__ yv,
    const float* __restrict__ g12, const float* __restrict__ g34,
    const float* __restrict__ g3412, const float* __restrict__ s1p,
    const float* __restrict__ s2p, int n, float* __restrict__ out) {
    __shared__ float s_sc[13];
    __shared__ float2 s_cw[NQ];
    __shared__ double sd[TPB];
    __shared__ int s_last;

    const int tid = threadIdx.x;

    if (tid == 0) {
        const float a = g12[0], b = g12[1], c = g12[2], d = g12[3];
        const float inv_det = 1.0f / (a * d - b * c);
        const float i00 = d * inv_det, i01 = -b * inv_det;
        const float i10 = -c * inv_det, i11 = a * inv_det;
        const float t0 = g3412[0], t1 = g3412[1], t2 = g3412[2], t3 = g3412[3];
        const float M00 = t0 * i00 + t1 * i10, M01 = t0 * i01 + t1 * i11;
        const float M10 = t2 * i00 + t3 * i10, M11 = t2 * i01 + t3 * i11;
        const float gs00 = g34[0] - (M00 * t0 + M01 * t1);
        const float gs01 = g34[1] - (M00 * t2 + M01 * t3);
        const float gs11 = g34[3] - (M10 * t2 + M11 * t3);
        const float s1g = sqrtf(gs00), s2g = sqrtf(gs11);
        const float rho = gs01 / (s1g * s2g);
        s_sc[0] = M00; s_sc[1] = M01; s_sc[2] = M10; s_sc[3] = M11;
        s_sc[4] = i00; s_sc[5] = i01 + i10; s_sc[6] = i11;
        s_sc[7] = 1.0f / s1g; s_sc[8] = 1.0f / s2g;
        s_sc[9] = (rho >= 0.0f) ? 1.0f : -1.0f;
        s_sc[10] = 1.0f / s1p[0];
        s_sc[11] = 1.0f / s2p[0];
        s_sc[12] = 2.0f * rho;
    }
    __syncthreads();
    if (tid < NQ) {
        const float rho = 0.5f * s_sc[12];
        const float hx = hx_of(tid);
        const float w = gw_of(tid);
        const float r = rho * hx;
        const float omr2 = 1.0f - r * r;
        float2 cw;
        cw.x = 1.4426950408889634f / (2.0f * omr2);
        const float amp = w * fabsf(rho) * 0.5f / (6.283185307179586f * sqrtf(omr2));
        cw.y = __log2f(amp);
        s_cw[tid] = cw;
    }
    __syncthreads();

    const float M00 = s_sc[0], M01 = s_sc[1], M10 = s_sc[2], M11 = s_sc[3];
    const float i00 = s_sc[4], i01s = s_sc[5], i11 = s_sc[6];
    const float inv_s1g = s_sc[7], inv_s2g = s_sc[8], sgn = s_sc[9];
    const float inv_sig1 = s_sc[10], inv_sig2 = s_sc[11], rho2 = s_sc[12];

    const int quarter = n >> 2;
    const float4* p3p = (const float4*)yhat;
    const float4* m1p = (const float4*)(yhat + n);
    const float4* p4p = (const float4*)(yhat + 2 * n);
    const float4* m2p = (const float4*)(yhat + 3 * n);
    const float4* l3p = (const float4*)yv;
    const float4* r1p = (const float4*)(yv + n);
    const float4* l4p = (const float4*)(yv + 2 * n);
    const float4* r2p = (const float4*)(yv + 3 * n);

    float tsum = 0.0f;
    const int gid = blockIdx.x * blockDim.x + tid;
    const int stride = gridDim.x * blockDim.x;
    for (int i = gid; i < quarter; i += stride) {
        const float4 v_p3 = __ldg(p3p + i);
        const float4 v_p4 = __ldg(p4p + i);
        const float4 v_m1 = __ldg(m1p + i);
        const float4 v_m2 = __ldg(m2p + i);
        const float4 v_r1 = __ldg(r1p + i);
        const float4 v_r2 = __ldg(r2p + i);
        const float4 v_l3 = __ldg(l3p + i);
        const float4 v_l4 = __ldg(l4p + i);

        float p3[4], p4[4], m1[4], m2[4], r1[4], r2[4], l3[4], l4[4];
        F4A(p3, v_p3); F4A(p4, v_p4); F4A(m1, v_m1); F4A(m2, v_m2);
        F4A(r1, v_r1); F4A(r2, v_r2); F4A(l3, v_l3); F4A(l4, v_l4);

        float P3[4], P4[4], HK[4], mS[4], quad[4];
#pragma unroll
        for (int l = 0; l < 4; l++) {
            const float e1 = (r1[l] - m1[l]) * inv_sig1;
            const float e2 = (r2[l] - m2[l]) * inv_sig2;
            const float mu1 = fmaf(M00, e1, M01 * e2);
            const float mu2 = fmaf(M10, e1, M11 * e2);
            quad[l] = fmaf(i00 * e1, e1, fmaf(i01s * e1, e2, i11 * e2 * e2));
            const float h = (ninv_q(0.5f - p3[l]) - mu1) * inv_s1g;
            const float k = (ninv_q(0.5f - p4[l]) - mu2) * inv_s2g;
            const float h2 = h * h, k2 = k * k;
            const float eh = ex2f(-0.72134752044448170f * h2);
            const float ek = ex2f(-0.72134752044448170f * k2);
            P3[l] = phi_fast(h, eh);
            P4[l] = phi_fast(k, ek);
            mS[l] = -(h2 + k2);
            HK[l] = rho2 * h * k;
        }

        float acc[4] = {0.0f, 0.0f, 0.0f, 0.0f};
#pragma unroll
        for (int q = 0; q < NQ; q++) {
            const float2 cw = s_cw[q];
#pragma unroll
            for (int l = 0; l < 4; l++) {
                acc[l] += ex2f(fmaf(cw.x, fmaf(HK[l], hx_of(q), mS[l]), cw.y));
            }
        }

#pragma unroll
        for (int l = 0; l < 4; l++) {
            const float B = fmaf(P3[l], P4[l], sgn * acc[l]);
            const bool b3 = !(l3[l] < 1.0f);
            const bool b4 = !(l4[l] < 1.0f);
            const float Ci = b3 ? (b4 ? (1.0f - P3[l] - P4[l] + B) : (P4[l] - B))
                                : (b4 ? (P3[l] - B) : B);
            tsum += fmaf(-0.5f, quad[l], __logf(fmaxf(Ci, 1e-30f)));
        }
    }

    // remainder (n % 4) handled by global thread 0
    if ((n & 3) && gid == 0) {
        for (int i = n & ~3; i < n; i++) {
            const float e1 = (yv[n + i] - yhat[n + i]) * inv_sig1;
            const float e2 = (yv[3 * n + i] - yhat[3 * n + i]) * inv_sig2;
            const float mu1 = fmaf(M00, e1, M01 * e2);
            const float mu2 = fmaf(M10, e1, M11 * e2);
            const float quad = fmaf(i00 * e1, e1, fmaf(i01s * e1, e2, i11 * e2 * e2));
            const float h = (ninv_q(0.5f - yhat[i]) - mu1) * inv_s1g;
            const float k = (ninv_q(0.5f - yhat[2 * n + i]) - mu2) * inv_s2g;
            const float h2 = h * h, k2 = k * k;
            const float P3 = phi_fast(h, ex2f(-0.72134752044448170f * h2));
            const float P4 = phi_fast(k, ex2f(-0.72134752044448170f * k2));
            const float mS = -(h2 + k2);
            const float HK = rho2 * h * k;
            float acc = 0.0f;
#pragma unroll
            for (int q = 0; q < NQ; q++) {
                const float2 cw = s_cw[q];
                acc += ex2f(fmaf(cw.x, fmaf(HK, hx_of(q), mS), cw.y));
            }
            const float B = fmaf(P3, P4, sgn * acc);
            const bool b3 = !(yv[i] < 1.0f), b4 = !(yv[2 * n + i] < 1.0f);
            const float Ci = b3 ? (b4 ? (1.0f - P3 - P4 + B) : (P4 - B))
                                : (b4 ? (P3 - B) : B);
            tsum += fmaf(-0.5f, quad, __logf(fmaxf(Ci, 1e-30f)));
        }
    }

    // ---- deterministic block reduction ----
    sd[tid] = (double)tsum;
    __syncthreads();
#pragma unroll
    for (int s = TPB / 2; s > 0; s >>= 1) {
        if (tid < s) sd[tid] += sd[tid + s];
        __syncthreads();
    }
    if (tid == 0) {
        d_part[blockIdx.x] = sd[0];
        __threadfence();
        const unsigned int old = atomicAdd(&d_count, 1u);
        s_last = (old == gridDim.x - 1) ? 1 : 0;
    }
    __syncthreads();

    if (s_last) {
        double v = 0.0;
        for (int j = tid; j < NBLOCKS; j += TPB) v += d_part[j];
        sd[tid] = v;
        __syncthreads();
#pragma unroll
        for (int s = TPB / 2; s > 0; s >>= 1) {
            if (tid < s) sd[tid] += sd[tid + s];
            __syncthreads();
        }
        if (tid == 0) {
            out[0] = (float)(-sd[0]);
            d_count = 0;
        }
    }
}

extern "C" void kernel_launch(void* const* d_in, const int* in_sizes, int n_in,
                              void* d_out, int out_size) {
    const float* yhat = (const float*)d_in[0];
    const float* yv = (const float*)d_in[1];
    const float* g12 = (const float*)d_in[2];
    const float* g34 = (const float*)d_in[3];
    const float* g3412 = (const float*)d_in[4];
    const float* s1 = (const float*)d_in[5];
    const float* s2 = (const float*)d_in[6];
    const int n = in_sizes[0] / 4;

    loss_kernel<<<NBLOCKS, TPB>>>(yhat, yv, g12, g34, g3412, s1, s2, n, (float*)d_out);
}

// round 7
// speedup vs baseline: 1.3576x; 1.3576x over previous
#include <cuda_runtime.h>
#include <math.h>

#define NQ 8
#define NBLOCKS 592
#define TPB 256

// ---- 8-point Gauss-Legendre (positive half; symmetric) ----
__device__ constexpr float GLX4[4] = {
    0.18343464249564980f, 0.52553240991632899f, 0.79666647741362674f, 0.96028985649753623f};
__device__ constexpr float GLW4[4] = {
    0.36268378337836198f, 0.31370664587788729f, 0.22238103445337447f, 0.10122853629037626f};

__device__ constexpr float hx_of(int q) {
    return (q < 4) ? 0.5f * (1.0f - GLX4[3 - q]) : 0.5f * (1.0f + GLX4[q - 4]);
}
__device__ constexpr float gw_of(int q) {
    return (q < 4) ? GLW4[3 - q] : GLW4[q - 4];
}

__device__ double d_part[NBLOCKS];
__device__ unsigned int d_count;   // zero-init; reset by last block each launch

__device__ __forceinline__ float ex2f(float x) {
    float y;
    asm("ex2.approx.ftz.f32 %0, %1;" : "=f"(y) : "f"(x));
    return y;
}
__device__ __forceinline__ float rcpf(float x) {
    float y;
    asm("rcp.approx.ftz.f32 %0, %1;" : "=f"(y) : "f"(x));
    return y;
}

// Acklam inverse-normal-CDF central region, takes q = p - 0.5 (|q| <= 0.45).
__device__ __forceinline__ float ninv_q(float q) {
    const float r = q * q;
    float num = fmaf(-3.969683028665376e+01f, r, 2.209460984245205e+02f);
    num = fmaf(num, r, -2.759285104469687e+02f);
    num = fmaf(num, r, 1.383577518672690e+02f);
    num = fmaf(num, r, -3.066479806614716e+01f);
    num = fmaf(num, r, 2.506628277459239e+00f);
    float den = fmaf(-5.447609879822406e+01f, r, 1.615858368580409e+02f);
    den = fmaf(den, r, -1.556989798598866e+02f);
    den = fmaf(den, r, 6.680131188771972e+01f);
    den = fmaf(den, r, -1.328068155288572e+01f);
    den = fmaf(den, r, 1.0f);
    return q * num * rcpf(den);
}

// Phi(h) via A&S 7.1.26 erfc (abs err <= 1.5e-7); eneg = exp(-h^2/2).
__device__ __forceinline__ float phi_fast(float h, float eneg) {
    const float z = fabsf(h) * 0.70710678118654752f;
    const float t = rcpf(fmaf(0.3275911f, z, 1.0f));
    float poly = fmaf(1.061405429f, t, -1.453152027f);
    poly = fmaf(poly, t, 1.421413741f);
    poly = fmaf(poly, t, -0.284496736f);
    poly = fmaf(poly, t, 0.254829592f);
    const float half_erfc = 0.5f * poly * t * eneg;
    return (h >= 0.0f) ? (1.0f - half_erfc) : half_erfc;
}

__global__ __launch_bounds__(TPB, 4) void loss_kernel(
    const float* __restrict__ yhat, const float* __restrict__ yv,
    const float* __restrict__ g12, const float* __restrict__ g34,
    const float* __restrict__ g3412, const float* __restrict__ s1p,
    const float* __restrict__ s2p, int n, float* __restrict__ out) {
    __shared__ float s_sc[13];
    __shared__ float2 s_cw[NQ];
    __shared__ double sd[TPB];
    __shared__ int s_last;

    const int tid = threadIdx.x;

    if (tid == 0) {
        const float a = g12[0], b = g12[1], c = g12[2], d = g12[3];
        const float inv_det = 1.0f / (a * d - b * c);
        const float i00 = d * inv_det, i01 = -b * inv_det;
        const float i10 = -c * inv_det, i11 = a * inv_det;
        const float t0 = g3412[0], t1 = g3412[1], t2 = g3412[2], t3 = g3412[3];
        const float M00 = t0 * i00 + t1 * i10, M01 = t0 * i01 + t1 * i11;
        const float M10 = t2 * i00 + t3 * i10, M11 = t2 * i01 + t3 * i11;
        const float gs00 = g34[0] - (M00 * t0 + M01 * t1);
        const float gs01 = g34[1] - (M00 * t2 + M01 * t3);
        const float gs11 = g34[3] - (M10 * t2 + M11 * t3);
        const float s1g = sqrtf(gs00), s2g = sqrtf(gs11);
        const float rho = gs01 / (s1g * s2g);
        s_sc[0] = M00; s_sc[1] = M01; s_sc[2] = M10; s_sc[3] = M11;
        s_sc[4] = i00; s_sc[5] = i01 + i10; s_sc[6] = i11;
        s_sc[7] = 1.0f / s1g; s_sc[8] = 1.0f / s2g;
        s_sc[9] = (rho >= 0.0f) ? 1.0f : -1.0f;
        s_sc[10] = 1.0f / s1p[0];
        s_sc[11] = 1.0f / s2p[0];
        s_sc[12] = 2.0f * rho;
    }
    __syncthreads();
    if (tid < NQ) {
        const float rho = 0.5f * s_sc[12];
        const float hx = hx_of(tid);
        const float w = gw_of(tid);
        const float r = rho * hx;
        const float omr2 = 1.0f - r * r;
        float2 cw;
        cw.x = 1.4426950408889634f / (2.0f * omr2);
        const float amp = w * fabsf(rho) * 0.5f / (6.283185307179586f * sqrtf(omr2));
        cw.y = __log2f(amp);
        s_cw[tid] = cw;
    }
    __syncthreads();

    const float M00 = s_sc[0], M01 = s_sc[1], M10 = s_sc[2], M11 = s_sc[3];
    const float i00 = s_sc[4], i01s = s_sc[5], i11 = s_sc[6];
    const float inv_s1g = s_sc[7], inv_s2g = s_sc[8], sgn = s_sc[9];
    const float inv_sig1 = s_sc[10], inv_sig2 = s_sc[11], rho2 = s_sc[12];

    const int half = n >> 1;
    const float2* p3p = (const float2*)yhat;
    const float2* m1p = (const float2*)(yhat + n);
    const float2* p4p = (const float2*)(yhat + 2 * n);
    const float2* m2p = (const float2*)(yhat + 3 * n);
    const float2* l3p = (const float2*)yv;
    const float2* r1p = (const float2*)(yv + n);
    const float2* l4p = (const float2*)(yv + 2 * n);
    const float2* r2p = (const float2*)(yv + 3 * n);

    float tsum = 0.0f;
    const int gid = blockIdx.x * blockDim.x + tid;
    const int stride = gridDim.x * blockDim.x;

    // ---- software-pipelined grid-stride loop ----
    float2 p3, p4, m1, m2, r1, r2, l3, l4;
    int i = gid;
    if (i < half) {
        p3 = __ldg(p3p + i); p4 = __ldg(p4p + i);
        m1 = __ldg(m1p + i); m2 = __ldg(m2p + i);
        r1 = __ldg(r1p + i); r2 = __ldg(r2p + i);
        l3 = __ldg(l3p + i); l4 = __ldg(l4p + i);
    }
    while (i < half) {
        // ---- preamble: consume loaded registers ----
        const float e1a = (r1.x - m1.x) * inv_sig1;
        const float e2a = (r2.x - m2.x) * inv_sig2;
        const float mu1a = fmaf(M00, e1a, M01 * e2a);
        const float mu2a = fmaf(M10, e1a, M11 * e2a);
        const float quada = fmaf(i00 * e1a, e1a, fmaf(i01s * e1a, e2a, i11 * e2a * e2a));
        const float ha = (ninv_q(0.5f - p3.x) - mu1a) * inv_s1g;
        const float ka = (ninv_q(0.5f - p4.x) - mu2a) * inv_s2g;

        const float e1b = (r1.y - m1.y) * inv_sig1;
        const float e2b = (r2.y - m2.y) * inv_sig2;
        const float mu1b = fmaf(M00, e1b, M01 * e2b);
        const float mu2b = fmaf(M10, e1b, M11 * e2b);
        const float quadb = fmaf(i00 * e1b, e1b, fmaf(i01s * e1b, e2b, i11 * e2b * e2b));
        const float hb = (ninv_q(0.5f - p3.y) - mu1b) * inv_s1g;
        const float kb = (ninv_q(0.5f - p4.y) - mu2b) * inv_s2g;

        const bool b3a = !(l3.x < 1.0f), b4a = !(l4.x < 1.0f);
        const bool b3b = !(l3.y < 1.0f), b4b = !(l4.y < 1.0f);

        // ---- prefetch next iteration into the now-dead load registers ----
        // Unconditional loads with a clamped in-bounds index: values are
        // unused when the loop exits, and keeping the LDGs branch-free lets
        // the scheduler batch them behind the math below.
        const int inext = i + stride;
        const int ipf = (inext < half) ? inext : i;
        p3 = __ldg(p3p + ipf); p4 = __ldg(p4p + ipf);
        m1 = __ldg(m1p + ipf); m2 = __ldg(m2p + ipf);
        r1 = __ldg(r1p + ipf); r2 = __ldg(r2p + ipf);
        l3 = __ldg(l3p + ipf); l4 = __ldg(l4p + ipf);

        // ---- main math overlaps the prefetch latency ----
        const float h2a = ha * ha, k2a = ka * ka;
        const float eha = ex2f(-0.72134752044448170f * h2a);
        const float eka = ex2f(-0.72134752044448170f * k2a);
        const float P3a = phi_fast(ha, eha);
        const float P4a = phi_fast(ka, eka);
        const float mSa = -(h2a + k2a);
        const float HKa = rho2 * ha * ka;

        const float h2b = hb * hb, k2b = kb * kb;
        const float ehb = ex2f(-0.72134752044448170f * h2b);
        const float ekb = ex2f(-0.72134752044448170f * k2b);
        const float P3b = phi_fast(hb, ehb);
        const float P4b = phi_fast(kb, ekb);
        const float mSb = -(h2b + k2b);
        const float HKb = rho2 * hb * kb;

        float a0 = 0.0f, a1 = 0.0f, b0 = 0.0f, b1 = 0.0f;
#pragma unroll
        for (int q = 0; q < NQ; q += 2) {
            const float2 cw0 = s_cw[q];
            const float2 cw1 = s_cw[q + 1];
            a0 += ex2f(fmaf(cw0.x, fmaf(HKa, hx_of(q), mSa), cw0.y));
            b0 += ex2f(fmaf(cw0.x, fmaf(HKb, hx_of(q), mSb), cw0.y));
            a1 += ex2f(fmaf(cw1.x, fmaf(HKa, hx_of(q + 1), mSa), cw1.y));
            b1 += ex2f(fmaf(cw1.x, fmaf(HKb, hx_of(q + 1), mSb), cw1.y));
        }
        const float Ba = fmaf(P3a, P4a, sgn * (a0 + a1));
        const float Bb = fmaf(P3b, P4b, sgn * (b0 + b1));

        const float Cia = b3a ? (b4a ? (1.0f - P3a - P4a + Ba) : (P4a - Ba))
                              : (b4a ? (P3a - Ba) : Ba);
        const float Cib = b3b ? (b4b ? (1.0f - P3b - P4b + Bb) : (P4b - Bb))
                              : (b4b ? (P3b - Bb) : Bb);

        tsum += fmaf(-0.5f, quada, __logf(fmaxf(Cia, 1e-30f)));
        tsum += fmaf(-0.5f, quadb, __logf(fmaxf(Cib, 1e-30f)));

        i = inext;
    }

    // odd-n tail: one scalar element handled by global thread 0
    if ((n & 1) && gid == 0) {
        const int j = n - 1;
        const float e1 = (yv[n + j] - yhat[n + j]) * inv_sig1;
        const float e2 = (yv[3 * n + j] - yhat[3 * n + j]) * inv_sig2;
        const float mu1 = fmaf(M00, e1, M01 * e2);
        const float mu2 = fmaf(M10, e1, M11 * e2);
        const float quad = fmaf(i00 * e1, e1, fmaf(i01s * e1, e2, i11 * e2 * e2));
        const float h = (ninv_q(0.5f - yhat[j]) - mu1) * inv_s1g;
        const float k = (ninv_q(0.5f - yhat[2 * n + j]) - mu2) * inv_s2g;
        const float h2 = h * h, k2 = k * k;
        const float P3 = phi_fast(h, ex2f(-0.72134752044448170f * h2));
        const float P4 = phi_fast(k, ex2f(-0.72134752044448170f * k2));
        const float mS = -(h2 + k2);
        const float HK = rho2 * h * k;
        float acc = 0.0f;
#pragma unroll
        for (int q = 0; q < NQ; q++) {
            const float2 cw = s_cw[q];
            acc += ex2f(fmaf(cw.x, fmaf(HK, hx_of(q), mS), cw.y));
        }
        const float B = fmaf(P3, P4, sgn * acc);
        const bool b3 = !(yv[j] < 1.0f), b4 = !(yv[2 * n + j] < 1.0f);
        const float Ci = b3 ? (b4 ? (1.0f - P3 - P4 + B) : (P4 - B))
                            : (b4 ? (P3 - B) : B);
        tsum += fmaf(-0.5f, quad, __logf(fmaxf(Ci, 1e-30f)));
    }

    // ---- deterministic block reduction ----
    sd[tid] = (double)tsum;
    __syncthreads();
#pragma unroll
    for (int s = TPB / 2; s > 0; s >>= 1) {
        if (tid < s) sd[tid] += sd[tid + s];
        __syncthreads();
    }
    if (tid == 0) {
        d_part[blockIdx.x] = sd[0];
        __threadfence();
        const unsigned int old = atomicAdd(&d_count, 1u);
        s_last = (old == gridDim.x - 1) ? 1 : 0;
    }
    __syncthreads();

    if (s_last) {
        double v = 0.0;
        for (int j = tid; j < NBLOCKS; j += TPB) v += d_part[j];
        sd[tid] = v;
        __syncthreads();
#pragma unroll
        for (int s = TPB / 2; s > 0; s >>= 1) {
            if (tid < s) sd[tid] += sd[tid + s];
            __syncthreads();
        }
        if (tid == 0) {
            out[0] = (float)(-sd[0]);
            d_count = 0;
        }
    }
}

extern "C" void kernel_launch(void* const* d_in, const int* in_sizes, int n_in,
                              void* d_out, int out_size) {
    const float* yhat = (const float*)d_in[0];
    const float* yv = (const float*)d_in[1];
    const float* g12 = (const float*)d_in[2];
    const float* g34 = (const float*)d_in[3];
    const float* g3412 = (const float*)d_in[4];
    const float* s1 = (const float*)d_in[5];
    const float* s2 = (const float*)d_in[6];
    const int n = in_sizes[0] / 4;

    loss_kernel<<<NBLOCKS, TPB>>>(yhat, yv, g12, g34, g3412, s1, s2, n, (float*)d_out);
}

// round 8
// speedup vs baseline: 1.4043x; 1.0344x over previous
#include <cuda_runtime.h>
#include <math.h>

#define NQ 4
#define NBLOCKS 592
#define TPB 256

// ---- 4-point Gauss-Legendre (positive half; symmetric) ----
__device__ constexpr float GLX2[2] = {0.33998104358485626f, 0.86113631159405258f};
__device__ constexpr float GLW2[2] = {0.65214515486254614f, 0.34785484513745386f};

// hx = (x+1)/2 for node index q in [0,4) (first 2 negative nodes, then positive)
__device__ constexpr float hx_of(int q) {
    return (q < 2) ? 0.5f * (1.0f - GLX2[1 - q]) : 0.5f * (1.0f + GLX2[q - 2]);
}
__device__ constexpr float gw_of(int q) {
    return (q < 2) ? GLW2[1 - q] : GLW2[q - 2];
}

__device__ double d_part[NBLOCKS];
__device__ unsigned int d_count;   // zero-init; reset by last block each launch

__device__ __forceinline__ float ex2f(float x) {
    float y;
    asm("ex2.approx.ftz.f32 %0, %1;" : "=f"(y) : "f"(x));
    return y;
}
__device__ __forceinline__ float rcpf(float x) {
    float y;
    asm("rcp.approx.ftz.f32 %0, %1;" : "=f"(y) : "f"(x));
    return y;
}

// Acklam inverse-normal-CDF central region, takes q = p - 0.5 (|q| <= 0.45).
__device__ __forceinline__ float ninv_q(float q) {
    const float r = q * q;
    float num = fmaf(-3.969683028665376e+01f, r, 2.209460984245205e+02f);
    num = fmaf(num, r, -2.759285104469687e+02f);
    num = fmaf(num, r, 1.383577518672690e+02f);
    num = fmaf(num, r, -3.066479806614716e+01f);
    num = fmaf(num, r, 2.506628277459239e+00f);
    float den = fmaf(-5.447609879822406e+01f, r, 1.615858368580409e+02f);
    den = fmaf(den, r, -1.556989798598866e+02f);
    den = fmaf(den, r, 6.680131188771972e+01f);
    den = fmaf(den, r, -1.328068155288572e+01f);
    den = fmaf(den, r, 1.0f);
    return q * num * rcpf(den);
}

// Phi(h) via A&S 7.1.26 erfc (abs err <= 1.5e-7); eneg = exp(-h^2/2).
__device__ __forceinline__ float phi_fast(float h, float eneg) {
    const float z = fabsf(h) * 0.70710678118654752f;
    const float t = rcpf(fmaf(0.3275911f, z, 1.0f));
    float poly = fmaf(1.061405429f, t, -1.453152027f);
    poly = fmaf(poly, t, 1.421413741f);
    poly = fmaf(poly, t, -0.284496736f);
    poly = fmaf(poly, t, 0.254829592f);
    const float half_erfc = 0.5f * poly * t * eneg;
    return (h >= 0.0f) ? (1.0f - half_erfc) : half_erfc;
}

__global__ __launch_bounds__(TPB, 4) void loss_kernel(
    const float* __restrict__ yhat, const float* __restrict__ yv,
    const float* __restrict__ g12, const float* __restrict__ g34,
    const float* __restrict__ g3412, const float* __restrict__ s1p,
    const float* __restrict__ s2p, int n, float* __restrict__ out) {
    __shared__ float s_sc[13];
    __shared__ float2 s_cw[NQ];
    __shared__ double sd[TPB];
    __shared__ int s_last;

    const int tid = threadIdx.x;

    if (tid == 0) {
        const float a = g12[0], b = g12[1], c = g12[2], d = g12[3];
        const float inv_det = 1.0f / (a * d - b * c);
        const float i00 = d * inv_det, i01 = -b * inv_det;
        const float i10 = -c * inv_det, i11 = a * inv_det;
        const float t0 = g3412[0], t1 = g3412[1], t2 = g3412[2], t3 = g3412[3];
        const float M00 = t0 * i00 + t1 * i10, M01 = t0 * i01 + t1 * i11;
        const float M10 = t2 * i00 + t3 * i10, M11 = t2 * i01 + t3 * i11;
        const float gs00 = g34[0] - (M00 * t0 + M01 * t1);
        const float gs01 = g34[1] - (M00 * t2 + M01 * t3);
        const float gs11 = g34[3] - (M10 * t2 + M11 * t3);
        const float s1g = sqrtf(gs00), s2g = sqrtf(gs11);
        const float rho = gs01 / (s1g * s2g);
        s_sc[0] = M00; s_sc[1] = M01; s_sc[2] = M10; s_sc[3] = M11;
        s_sc[4] = i00; s_sc[5] = i01 + i10; s_sc[6] = i11;
        s_sc[7] = 1.0f / s1g; s_sc[8] = 1.0f / s2g;
        s_sc[9] = (rho >= 0.0f) ? 1.0f : -1.0f;
        s_sc[10] = 1.0f / s1p[0];
        s_sc[11] = 1.0f / s2p[0];
        s_sc[12] = 2.0f * rho;
    }
    __syncthreads();
    if (tid < NQ) {
        const float rho = 0.5f * s_sc[12];
        const float hx = hx_of(tid);
        const float w = gw_of(tid);
        const float r = rho * hx;
        const float omr2 = 1.0f - r * r;
        float2 cw;
        cw.x = 1.4426950408889634f / (2.0f * omr2);
        const float amp = w * fabsf(rho) * 0.5f / (6.283185307179586f * sqrtf(omr2));
        cw.y = __log2f(amp);
        s_cw[tid] = cw;
    }
    __syncthreads();

    const float M00 = s_sc[0], M01 = s_sc[1], M10 = s_sc[2], M11 = s_sc[3];
    const float i00 = s_sc[4], i01s = s_sc[5], i11 = s_sc[6];
    const float inv_s1g = s_sc[7], inv_s2g = s_sc[8], sgn = s_sc[9];
    const float inv_sig1 = s_sc[10], inv_sig2 = s_sc[11], rho2 = s_sc[12];

    const int half = n >> 1;
    const float2* p3p = (const float2*)yhat;
    const float2* m1p = (const float2*)(yhat + n);
    const float2* p4p = (const float2*)(yhat + 2 * n);
    const float2* m2p = (const float2*)(yhat + 3 * n);
    const float2* l3p = (const float2*)yv;
    const float2* r1p = (const float2*)(yv + n);
    const float2* l4p = (const float2*)(yv + 2 * n);
    const float2* r2p = (const float2*)(yv + 3 * n);

    float tsum = 0.0f;
    const int gid = blockIdx.x * blockDim.x + tid;
    const int stride = gridDim.x * blockDim.x;

    // ---- software-pipelined grid-stride loop ----
    float2 p3, p4, m1, m2, r1, r2, l3, l4;
    int i = gid;
    if (i < half) {
        p3 = __ldg(p3p + i); p4 = __ldg(p4p + i);
        m1 = __ldg(m1p + i); m2 = __ldg(m2p + i);
        r1 = __ldg(r1p + i); r2 = __ldg(r2p + i);
        l3 = __ldg(l3p + i); l4 = __ldg(l4p + i);
    }
    while (i < half) {
        // ---- preamble: consume loaded registers ----
        const float e1a = (r1.x - m1.x) * inv_sig1;
        const float e2a = (r2.x - m2.x) * inv_sig2;
        const float mu1a = fmaf(M00, e1a, M01 * e2a);
        const float mu2a = fmaf(M10, e1a, M11 * e2a);
        const float quada = fmaf(i00 * e1a, e1a, fmaf(i01s * e1a, e2a, i11 * e2a * e2a));
        const float ha = (ninv_q(0.5f - p3.x) - mu1a) * inv_s1g;
        const float ka = (ninv_q(0.5f - p4.x) - mu2a) * inv_s2g;

        const float e1b = (r1.y - m1.y) * inv_sig1;
        const float e2b = (r2.y - m2.y) * inv_sig2;
        const float mu1b = fmaf(M00, e1b, M01 * e2b);
        const float mu2b = fmaf(M10, e1b, M11 * e2b);
        const float quadb = fmaf(i00 * e1b, e1b, fmaf(i01s * e1b, e2b, i11 * e2b * e2b));
        const float hb = (ninv_q(0.5f - p3.y) - mu1b) * inv_s1g;
        const float kb = (ninv_q(0.5f - p4.y) - mu2b) * inv_s2g;

        const bool b3a = !(l3.x < 1.0f), b4a = !(l4.x < 1.0f);
        const bool b3b = !(l3.y < 1.0f), b4b = !(l4.y < 1.0f);

        // ---- prefetch next iteration into the now-dead load registers ----
        const int inext = i + stride;
        const int ipf = (inext < half) ? inext : i;
        p3 = __ldg(p3p + ipf); p4 = __ldg(p4p + ipf);
        m1 = __ldg(m1p + ipf); m2 = __ldg(m2p + ipf);
        r1 = __ldg(r1p + ipf); r2 = __ldg(r2p + ipf);
        l3 = __ldg(l3p + ipf); l4 = __ldg(l4p + ipf);

        // ---- main math overlaps the prefetch latency ----
        const float h2a = ha * ha, k2a = ka * ka;
        const float eha = ex2f(-0.72134752044448170f * h2a);
        const float eka = ex2f(-0.72134752044448170f * k2a);
        const float P3a = phi_fast(ha, eha);
        const float P4a = phi_fast(ka, eka);
        const float mSa = -(h2a + k2a);
        const float HKa = rho2 * ha * ka;

        const float h2b = hb * hb, k2b = kb * kb;
        const float ehb = ex2f(-0.72134752044448170f * h2b);
        const float ekb = ex2f(-0.72134752044448170f * k2b);
        const float P3b = phi_fast(hb, ehb);
        const float P4b = phi_fast(kb, ekb);
        const float mSb = -(h2b + k2b);
        const float HKb = rho2 * hb * kb;

        float a0 = 0.0f, a1 = 0.0f, b0 = 0.0f, b1 = 0.0f;
#pragma unroll
        for (int q = 0; q < NQ; q += 2) {
            const float2 cw0 = s_cw[q];
            const float2 cw1 = s_cw[q + 1];
            a0 += ex2f(fmaf(cw0.x, fmaf(HKa, hx_of(q), mSa), cw0.y));
            b0 += ex2f(fmaf(cw0.x, fmaf(HKb, hx_of(q), mSb), cw0.y));
            a1 += ex2f(fmaf(cw1.x, fmaf(HKa, hx_of(q + 1), mSa), cw1.y));
            b1 += ex2f(fmaf(cw1.x, fmaf(HKb, hx_of(q + 1), mSb), cw1.y));
        }
        const float Ba = fmaf(P3a, P4a, sgn * (a0 + a1));
        const float Bb = fmaf(P3b, P4b, sgn * (b0 + b1));

        const float Cia = b3a ? (b4a ? (1.0f - P3a - P4a + Ba) : (P4a - Ba))
                              : (b4a ? (P3a - Ba) : Ba);
        const float Cib = b3b ? (b4b ? (1.0f - P3b - P4b + Bb) : (P4b - Bb))
                              : (b4b ? (P3b - Bb) : Bb);

        // paired log: one lg2 per two elements
        const float prod = fmaxf(Cia, 1e-30f) * fmaxf(Cib, 1e-30f);
        tsum += fmaf(-0.5f, quada + quadb, __logf(prod));

        i = inext;
    }

    // odd-n tail: one scalar element handled by global thread 0
    if ((n & 1) && gid == 0) {
        const int j = n - 1;
        const float e1 = (yv[n + j] - yhat[n + j]) * inv_sig1;
        const float e2 = (yv[3 * n + j] - yhat[3 * n + j]) * inv_sig2;
        const float mu1 = fmaf(M00, e1, M01 * e2);
        const float mu2 = fmaf(M10, e1, M11 * e2);
        const float quad = fmaf(i00 * e1, e1, fmaf(i01s * e1, e2, i11 * e2 * e2));
        const float h = (ninv_q(0.5f - yhat[j]) - mu1) * inv_s1g;
        const float k = (ninv_q(0.5f - yhat[2 * n + j]) - mu2) * inv_s2g;
        const float h2 = h * h, k2 = k * k;
        const float P3 = phi_fast(h, ex2f(-0.72134752044448170f * h2));
        const float P4 = phi_fast(k, ex2f(-0.72134752044448170f * k2));
        const float mS = -(h2 + k2);
        const float HK = rho2 * h * k;
        float acc = 0.0f;
#pragma unroll
        for (int q = 0; q < NQ; q++) {
            const float2 cw = s_cw[q];
            acc += ex2f(fmaf(cw.x, fmaf(HK, hx_of(q), mS), cw.y));
        }
        const float B = fmaf(P3, P4, sgn * acc);
        const bool b3 = !(yv[j] < 1.0f), b4 = !(yv[2 * n + j] < 1.0f);
        const float Ci = b3 ? (b4 ? (1.0f - P3 - P4 + B) : (P4 - B))
                            : (b4 ? (P3 - B) : B);
        tsum += fmaf(-0.5f, quad, __logf(fmaxf(Ci, 1e-30f)));
    }

    // ---- deterministic block reduction ----
    sd[tid] = (double)tsum;
    __syncthreads();
#pragma unroll
    for (int s = TPB / 2; s > 0; s >>= 1) {
        if (tid < s) sd[tid] += sd[tid + s];
        __syncthreads();
    }
    if (tid == 0) {
        d_part[blockIdx.x] = sd[0];
        __threadfence();
        const unsigned int old = atomicAdd(&d_count, 1u);
        s_last = (old == gridDim.x - 1) ? 1 : 0;
    }
    __syncthreads();

    if (s_last) {
        double v = 0.0;
        for (int j = tid; j < NBLOCKS; j += TPB) v += d_part[j];
        sd[tid] = v;
        __syncthreads();
#pragma unroll
        for (int s = TPB / 2; s > 0; s >>= 1) {
            if (tid < s) sd[tid] += sd[tid + s];
            __syncthreads();
        }
        if (tid == 0) {
            out[0] = (float)(-sd[0]);
            d_count = 0;
        }
    }
}

extern "C" void kernel_launch(void* const* d_in, const int* in_sizes, int n_in,
                              void* d_out, int out_size) {
    const float* yhat = (const float*)d_in[0];
    const float* yv = (const float*)d_in[1];
    const float* g12 = (const float*)d_in[2];
    const float* g34 = (const float*)d_in[3];
    const float* g3412 = (const float*)d_in[4];
    const float* s1 = (const float*)d_in[5];
    const float* s2 = (const float*)d_in[6];
    const int n = in_sizes[0] / 4;

    loss_kernel<<<NBLOCKS, TPB>>>(yhat, yv, g12, g34, g3412, s1, s2, n, (float*)d_out);
}